// round 12
// baseline (speedup 1.0000x reference)
#include <cuda_runtime.h>

#define NN 256
#define BB 2
#define NNODE (BB*NN)

#define RSQRT3 0.5773502691896258f
#define INV_FAN 0.1767766952966369f   // 1/sqrt(32)

#define PACK_F32X2(out, lo, hi) \
    asm("mov.b64 %0, {%1, %2};" : "=l"(out) : "f"(lo), "f"(hi))
#define UNPACK_F32X2(lo, hi, in) \
    asm("mov.b64 {%0, %1}, %2;" : "=f"(lo), "=f"(hi) : "l"(in))
#define FMA_F32X2(d, a, b, c) \
    asm("fma.rn.f32x2 %0, %1, %2, %3;" : "=l"(d) : "l"(a), "l"(b), "l"(c))
#define ADD_F32X2(d, a, b) \
    asm("add.rn.f32x2 %0, %1, %2;" : "=l"(d) : "l"(a), "l"(b))

#define CP_ASYNC16(dst_u32, src_ptr) \
    asm volatile("cp.async.ca.shared.global [%0], [%1], 16;" :: "r"(dst_u32), "l"(src_ptr))
#define CP_COMMIT() asm volatile("cp.async.commit_group;" ::: "memory")
#define CP_WAIT(n)  asm volatile("cp.async.wait_group %0;" :: "n"(n) : "memory")

// ---- smem layout (floats) ----
#define OFF_EA    0          // 4 buffers x 2048 (64 rows x 32) ; part[64][33] overlays
#define OFF_SHP   8192       // 256 x 4 premultiplied sh
#define OFF_W1S   9216       // 32 x 32
#define OFF_B1S   10240      // 32
#define OFF_GP    10272      // 8 x 132
#define OFF_GS    11328      // 132 (+pad 0) -> 16B aligned (11328*4 % 16 == 0)
#define OFF_SIN   11460      // 16
#define OFF_VIN   11476      // 48
#define OFF_WLS   11524      // 256
#define OFF_WLV   11780      // 256
#define OFF_WOS   12036      // 256
#define OFF_WOV   12292      // 256
#define OFF_OUTS  12548      // 16
#define OFF_OUTV  12564      // 48
#define OFF_RED   12612      // 8
#define OFF_DSUM  12620      // 1
#define OFF_W2ST  12624      // 3 buffers x 2048 (2 W2' rows each) ; 16B aligned
#define SMEM_FLOATS 18768
#define SMEM_BYTES  (SMEM_FLOATS * 4)

// ---------------------------------------------------------------------------
// Fused kernel: one block per node.
// Phase E: h = relu(ea@W1+b1); G[f,c] = sum_m h[m,f]*sh'[m,c] (G in smem)
// Phase N: contract G x {s_in,v_in} planes against W2' streamed in 17 chunks
// Epilogue: scale, output linear, residual.
// ---------------------------------------------------------------------------
__global__ __launch_bounds__(256, 3) void fused_kernel(
    const float* __restrict__ node_attr,
    const float* __restrict__ edge_attr,
    const float* __restrict__ edge_sh,
    const float* __restrict__ mask,
    const float* __restrict__ w_lin_in_s,
    const float* __restrict__ w_lin_in_v,
    const float* __restrict__ fc_w1,
    const float* __restrict__ fc_b1,
    const float* __restrict__ fc_w2,
    const float* __restrict__ fc_b2,
    const float* __restrict__ w_lin_out_s,
    const float* __restrict__ w_lin_out_v,
    float* __restrict__ out)
{
    extern __shared__ __align__(16) float sm[];
    const int node = blockIdx.x;
    const int b = node >> 8;
    const int n = node & 255;
    const int t = threadIdx.x;
    const int lane = t & 31;
    const int wid = t >> 5;

    const unsigned sm_u = (unsigned)__cvta_generic_to_shared(sm);
    const float* ea_g = edge_attr + (size_t)node * NN * 32;

    // ---- issue: 4 ea chunks (g0..g3), W2' chunks 0,1 (g4,g5) ----
    #pragma unroll
    for (int ch = 0; ch < 4; ch++) {
        #pragma unroll
        for (int k = 0; k < 2; k++) {
            int u = t + k * 256;
            int row = u >> 3, seg = u & 7;
            unsigned dst = sm_u + (unsigned)(OFF_EA + ch * 2048 + row * 32 + seg * 4) * 4u;
            CP_ASYNC16(dst, ea_g + (ch * 64 + row) * 32 + seg * 4);
        }
        CP_COMMIT();
    }
    #pragma unroll
    for (int c0 = 0; c0 < 2; c0++) {
        #pragma unroll
        for (int k = 0; k < 2; k++) {
            int u = t + k * 256;
            unsigned dst = sm_u + (unsigned)(OFF_W2ST + c0 * 2048 + u * 4) * 4u;
            CP_ASYNC16(dst, fc_w2 + c0 * 2048 + u * 4);
        }
        CP_COMMIT();
    }

    // ---- prologue staging (overlaps cp.async) ----
    ((float4*)(sm + OFF_W1S))[t] = ((const float4*)fc_w1)[t];
    if (t < 32) sm[OFF_B1S + t] = fc_b1[t];
    sm[OFF_WLS + t] = w_lin_in_s[t];
    sm[OFF_WLV + t] = w_lin_in_v[t];
    sm[OFF_WOS + t] = w_lin_out_s[t];
    sm[OFF_WOV + t] = w_lin_out_v[t];
    {
        float mf = mask[b * NN + t] * (t != n ? 1.0f : 0.0f);
        float4 s = ((const float4*)(edge_sh + (size_t)node * NN * 4))[t];
        s.x *= mf; s.y *= mf; s.z *= mf; s.w *= mf;
        ((float4*)(sm + OFF_SHP))[t] = s;
    }
    {
        float mv = mask[b * NN + t];
        #pragma unroll
        for (int o = 16; o; o >>= 1) mv += __shfl_xor_sync(0xFFFFFFFFu, mv, o);
        if (lane == 0) sm[OFF_RED + wid] = mv;
    }
    __syncthreads();
    if (t == 0) {
        float s = 0.f;
        #pragma unroll
        for (int i = 0; i < 8; i++) s += sm[OFF_RED + i];
        sm[OFF_DSUM] = s - 1.0f;
    }
    // s_in / v_in
    if (t < 64) {
        const float* na = node_attr + (size_t)node * 64;
        if (t < 16) {
            float s = 0.f;
            #pragma unroll
            for (int i = 0; i < 16; i++) s += na[i] * sm[OFF_WLS + i * 16 + t];
            sm[OFF_SIN + t] = s * 0.25f;
        } else {
            int idx = t - 16;
            int o = idx / 3, x = idx % 3;
            float s = 0.f;
            #pragma unroll
            for (int i = 0; i < 16; i++) s += na[16 + i * 3 + x] * sm[OFF_WLV + i * 16 + o];
            sm[OFF_VIN + o * 3 + x] = s * 0.25f;
        }
    }

    // ---- Phase E: edge reduction (lane = f, warp strides rows) ----
    unsigned long long w1p[16];
    #pragma unroll
    for (int j = 0; j < 16; j++)
        PACK_F32X2(w1p[j], sm[OFF_W1S + (2*j) * 32 + lane],
                           sm[OFF_W1S + (2*j+1) * 32 + lane]);
    unsigned long long bias2;
    PACK_F32X2(bias2, sm[OFF_B1S + lane], 0.0f);

    unsigned long long acc01 = 0ULL, acc23 = 0ULL;
    const ulonglong2* sh2 = (const ulonglong2*)(sm + OFF_SHP);

    #pragma unroll
    for (int ch = 0; ch < 4; ch++) {
        if (ch == 0)      { CP_WAIT(5); }
        else if (ch == 1) { CP_WAIT(4); }
        else if (ch == 2) { CP_WAIT(3); }
        else              { CP_WAIT(2); }
        __syncthreads();
        const float* buf = sm + OFF_EA + ch * 2048;
        #pragma unroll
        for (int it = 0; it < 8; it++) {
            int r = wid + it * 8;
            const ulonglong2* row = (const ulonglong2*)(buf + r * 32);
            unsigned long long c0 = bias2, c1 = 0ULL, c2 = 0ULL, c3 = 0ULL;
            ulonglong2 u0 = row[0];
            ulonglong2 u1 = row[1];
            ulonglong2 u2 = row[2];
            ulonglong2 u3 = row[3];
            FMA_F32X2(c0, u0.x, w1p[0], c0);
            FMA_F32X2(c1, u0.y, w1p[1], c1);
            FMA_F32X2(c2, u1.x, w1p[2], c2);
            FMA_F32X2(c3, u1.y, w1p[3], c3);
            u0 = row[4];
            u1 = row[5];
            FMA_F32X2(c0, u2.x, w1p[4], c0);
            FMA_F32X2(c1, u2.y, w1p[5], c1);
            FMA_F32X2(c2, u3.x, w1p[6], c2);
            FMA_F32X2(c3, u3.y, w1p[7], c3);
            u2 = row[6];
            u3 = row[7];
            FMA_F32X2(c0, u0.x, w1p[8],  c0);
            FMA_F32X2(c1, u0.y, w1p[9],  c1);
            FMA_F32X2(c2, u1.x, w1p[10], c2);
            FMA_F32X2(c3, u1.y, w1p[11], c3);
            FMA_F32X2(c0, u2.x, w1p[12], c0);
            FMA_F32X2(c1, u2.y, w1p[13], c1);
            FMA_F32X2(c2, u3.x, w1p[14], c2);
            FMA_F32X2(c3, u3.y, w1p[15], c3);
            ADD_F32X2(c0, c0, c1);
            ADD_F32X2(c2, c2, c3);
            ADD_F32X2(c0, c0, c2);
            float lo, hi;
            UNPACK_F32X2(lo, hi, c0);
            float h = fmaxf(lo + hi, 0.0f);
            unsigned long long h2;
            PACK_F32X2(h2, h, h);
            ulonglong2 s2 = sh2[ch * 64 + r];
            FMA_F32X2(acc01, h2, s2.x, acc01);
            FMA_F32X2(acc23, h2, s2.y, acc23);
        }
    }
    {
        float o0, o1, o2, o3;
        UNPACK_F32X2(o0, o1, acc01);
        UNPACK_F32X2(o2, o3, acc23);
        *(float4*)(sm + OFF_GP + wid * 132 + lane * 4) = make_float4(o0, o1, o2, o3);
    }
    // bias feature G[32][c]
    if (t < 32) {
        int cc = t & 3, mq = t >> 2;
        float s = 0.f;
        #pragma unroll 8
        for (int m = mq; m < 256; m += 8) s += sm[OFF_SHP + m * 4 + cc];
        sm[OFF_GP + mq * 132 + 128 + cc] = s;
    }
    __syncthreads();
    if (t < 132) {
        float s = 0.f;
        #pragma unroll
        for (int g2 = 0; g2 < 8; g2++) s += sm[OFF_GP + g2 * 132 + t];
        sm[OFF_GS + t] = s;
    }

    // ---- Phase N: stream W2' in 17 chunks of 2 rows (3 buffers) ----
    // thread mapping: fi = t>>3 (f_local = fi>>4, i = fi&15), oh = t&7
    const int fi = t >> 3;
    const int oh = t & 7;
    const int f_local = fi >> 4;
    const int i = fi & 15;
    const float si = sm[OFF_SIN + i];
    const float x0 = sm[OFF_VIN + i * 3 + 0];
    const float x1 = sm[OFF_VIN + i * 3 + 1];
    const float x2 = sm[OFF_VIN + i * 3 + 2];

    unsigned long long accS = 0ULL;
    unsigned long long accV[3] = {0ULL, 0ULL, 0ULL};

    #pragma unroll 4
    for (int c = 0; c < 17; c++) {
        if (c < 16) { CP_WAIT(1); } else { CP_WAIT(0); }
        __syncthreads();
        // refill buffer (c+2)%3 (last used by chunk c-1, whose compute is done)
        if (c + 2 <= 16) {
            int nc = c + 2;
            unsigned dst = sm_u + (unsigned)(OFF_W2ST + (nc % 3) * 2048) * 4u;
            if (nc < 16) {
                #pragma unroll
                for (int k = 0; k < 2; k++) {
                    int u = t + k * 256;
                    CP_ASYNC16(dst + (unsigned)u * 16u, fc_w2 + nc * 2048 + u * 4);
                }
            } else {
                CP_ASYNC16(dst + (unsigned)t * 16u, fc_b2 + t * 4);
            }
            CP_COMMIT();
        }
        // compute chunk c
        if (c < 16 || f_local == 0) {
            int f_glob = (c < 16) ? (c * 2 + f_local) : 32;
            const float* Wb = sm + OFF_W2ST + (c % 3) * 2048
                              + f_local * 1024 + i * 16 + oh * 2;
            unsigned long long wss = *(const unsigned long long*)(Wb);
            unsigned long long wvv = *(const unsigned long long*)(Wb + 256);
            unsigned long long wsv = *(const unsigned long long*)(Wb + 512);
            unsigned long long wvs = *(const unsigned long long*)(Wb + 768);
            float4 gv = *(const float4*)(sm + OFF_GS + f_glob * 4);
            float a  = gv.x * si;
            float bc = (gv.y * x0 + gv.z * x1 + gv.w * x2) * RSQRT3;
            float c0 = gv.y * si, c1 = gv.z * si, c2 = gv.w * si;
            float d0 = gv.x * x0, d1 = gv.x * x1, d2 = gv.x * x2;
            unsigned long long a2, bc2, p0, p1, p2, q0, q1, q2;
            PACK_F32X2(a2, a, a);    PACK_F32X2(bc2, bc, bc);
            PACK_F32X2(p0, c0, c0);  PACK_F32X2(p1, c1, c1);  PACK_F32X2(p2, c2, c2);
            PACK_F32X2(q0, d0, d0);  PACK_F32X2(q1, d1, d1);  PACK_F32X2(q2, d2, d2);
            FMA_F32X2(accS, a2,  wss, accS);
            FMA_F32X2(accS, bc2, wvv, accS);
            FMA_F32X2(accV[0], p0, wsv, accV[0]);
            FMA_F32X2(accV[0], q0, wvs, accV[0]);
            FMA_F32X2(accV[1], p1, wsv, accV[1]);
            FMA_F32X2(accV[1], q1, wvs, accV[1]);
            FMA_F32X2(accV[2], p2, wsv, accV[2]);
            FMA_F32X2(accV[2], q2, wvs, accV[2]);
        }
    }
    __syncthreads();   // all reads of ea/shp/W2 regions done

    // ---- stage partials: part[out 0..63][fi 0..31], pitch 33 (overlays ea) ----
    {
        float v0, v1;
        UNPACK_F32X2(v0, v1, accS);
        sm[OFF_EA + (oh * 2 + 0) * 33 + fi] = v0;
        sm[OFF_EA + (oh * 2 + 1) * 33 + fi] = v1;
        #pragma unroll
        for (int x = 0; x < 3; x++) {
            UNPACK_F32X2(v0, v1, accV[x]);
            sm[OFF_EA + (16 + (oh * 2 + 0) * 3 + x) * 33 + fi] = v0;
            sm[OFF_EA + (16 + (oh * 2 + 1) * 3 + x) * 33 + fi] = v1;
        }
    }
    __syncthreads();

    // ---- reduce 32 partials per output, scale ----
    if (t < 64) {
        float scale = INV_FAN / sm[OFF_DSUM];
        const float* row = sm + OFF_EA + t * 33;
        float s = 0.f;
        #pragma unroll
        for (int k = 0; k < 32; k++) s += row[k];
        if (t < 16) sm[OFF_OUTS + t] = s * scale;
        else        sm[OFF_OUTV + t - 16] = s * scale;
    }
    __syncthreads();

    // ---- output linear (/4) + residual ----
    if (t < 64) {
        const float* na = node_attr + (size_t)node * 64;
        float r;
        if (t < 16) {
            float s = 0.f;
            #pragma unroll
            for (int o = 0; o < 16; o++) s += sm[OFF_OUTS + o] * sm[OFF_WOS + o * 16 + t];
            r = s * 0.25f + na[t];
        } else {
            int idx = t - 16;
            int o2 = idx / 3, x = idx % 3;
            float s = 0.f;
            #pragma unroll
            for (int o = 0; o < 16; o++) s += sm[OFF_OUTV + o * 3 + x] * sm[OFF_WOV + o * 16 + o2];
            r = s * 0.25f + na[t];
        }
        out[(size_t)node * 64 + t] = r;
    }
}

extern "C" void kernel_launch(void* const* d_in, const int* in_sizes, int n_in,
                              void* d_out, int out_size) {
    const float* node_attr    = (const float*)d_in[0];
    const float* edge_attr    = (const float*)d_in[1];
    const float* edge_sh      = (const float*)d_in[2];
    const float* mask         = (const float*)d_in[3];
    const float* w_lin_in_s   = (const float*)d_in[4];
    const float* w_lin_in_v   = (const float*)d_in[5];
    const float* fc_w1        = (const float*)d_in[6];
    const float* fc_b1        = (const float*)d_in[7];
    const float* fc_w2        = (const float*)d_in[8];
    const float* fc_b2        = (const float*)d_in[9];
    const float* w_lin_out_s  = (const float*)d_in[10];
    const float* w_lin_out_v  = (const float*)d_in[11];
    float* out = (float*)d_out;

    cudaFuncSetAttribute(fused_kernel,
                         cudaFuncAttributeMaxDynamicSharedMemorySize, SMEM_BYTES);

    fused_kernel<<<NNODE, 256, SMEM_BYTES>>>(node_attr, edge_attr, edge_sh, mask,
                                             w_lin_in_s, w_lin_in_v,
                                             fc_w1, fc_b1, fc_w2, fc_b2,
                                             w_lin_out_s, w_lin_out_v, out);
}

// round 13
// speedup vs baseline: 1.0694x; 1.0694x over previous
#include <cuda_runtime.h>

#define NN 256
#define BB 2
#define NNODE (BB*NN)

#define RSQRT3 0.5773502691896258f
#define INV_FAN 0.1767766952966369f   // 1/sqrt(32)

// partial G: per (node, half) -> [f*4+c], f in [0,33), f==32 = bias feature
__device__ float g_G2[2*NNODE][132];

#define PACK_F32X2(out, lo, hi) \
    asm("mov.b64 %0, {%1, %2};" : "=l"(out) : "f"(lo), "f"(hi))
#define UNPACK_F32X2(lo, hi, in) \
    asm("mov.b64 {%0, %1}, %2;" : "=f"(lo), "=f"(hi) : "l"(in))
#define FMA_F32X2(d, a, b, c) \
    asm("fma.rn.f32x2 %0, %1, %2, %3;" : "=l"(d) : "l"(a), "l"(b), "l"(c))
#define ADD_F32X2(d, a, b) \
    asm("add.rn.f32x2 %0, %1, %2;" : "=l"(d) : "l"(a), "l"(b))

#define CP_ASYNC16(dst_u32, src_ptr) \
    asm volatile("cp.async.ca.shared.global [%0], [%1], 16;" :: "r"(dst_u32), "l"(src_ptr))
#define CP_COMMIT() asm volatile("cp.async.commit_group;" ::: "memory")
#define CP_WAIT2()  asm volatile("cp.async.wait_group 2;" ::: "memory")
#define CP_WAIT1()  asm volatile("cp.async.wait_group 1;" ::: "memory")
#define CP_WAIT0()  asm volatile("cp.async.wait_group 0;" ::: "memory")

// ---------------------------------------------------------------------------
// Kernel A: edge reduction, one block per (node, half): 128 m-rows per block.
// Dual-address mapping: lanes 0-15 -> row r0, lanes 16-31 -> row r1;
// each lane covers f-pair (2*fh, 2*fh+1) with j-packed f32x2 chains.
// r1's chunk order is rotated (jc^1) so each LDS.128 (2 addresses) is 1 wf.
// ---------------------------------------------------------------------------
__global__ __launch_bounds__(256, 2) void edge_kernel(
    const float* __restrict__ edge_attr,
    const float* __restrict__ edge_sh,
    const float* __restrict__ mask,
    const float* __restrict__ fc_w1,
    const float* __restrict__ fc_b1)
{
    __shared__ __align__(16) float eas[2][64 * 32];   // 2 x 8 KB
    __shared__ __align__(16) float shp[128 * 4];      // premultiplied sh
    __shared__ __align__(16) float w1s[1024];         // [j][f]
    __shared__ float b1s[32];
    __shared__ float Gp[8][132];

    const int blk  = blockIdx.x;
    const int node = blk >> 1;
    const int half = blk & 1;
    const int b = node >> 8;
    const int n = node & 255;
    const int m0 = half * 128;
    const int t = threadIdx.x;
    const int lane = t & 31;
    const int wid = t >> 5;

    const float* ea_g = edge_attr + (size_t)node * NN * 32 + (size_t)m0 * 32;
    const unsigned ea_u = (unsigned)__cvta_generic_to_shared(&eas[0][0]);

    // issue both 64-row chunks immediately
    CP_ASYNC16(ea_u + (unsigned)t * 16u, ea_g + t * 4);
    CP_ASYNC16(ea_u + 4096u + (unsigned)t * 16u, ea_g + 1024 + t * 4);
    CP_COMMIT();
    CP_ASYNC16(ea_u + 8192u + (unsigned)t * 16u, ea_g + 2048 + t * 4);
    CP_ASYNC16(ea_u + 12288u + (unsigned)t * 16u, ea_g + 3072 + t * 4);
    CP_COMMIT();

    // prologue staging (overlaps cp.async)
    ((float4*)w1s)[t] = ((const float4*)fc_w1)[t];
    if (t < 32) b1s[t] = fc_b1[t];
    if (t < 128) {
        int m = m0 + t;
        float mf = mask[b * NN + m] * (m != n ? 1.0f : 0.0f);
        float4 s = ((const float4*)(edge_sh + (size_t)node * NN * 4))[m];
        s.x *= mf; s.y *= mf; s.z *= mf; s.w *= mf;
        ((float4*)shp)[t] = s;
    }
    __syncthreads();

    const int fh   = lane & 15;
    const int side = lane >> 4;
    const int f0 = 2 * fh;
    const int f1 = f0 + 1;

    // hoist W1 j-pairs for both f's, in this lane's (rotated) read order
    unsigned long long w1a[16], w1b[16];
    #pragma unroll
    for (int k = 0; k < 16; k++) {
        int jc = k >> 1, h = k & 1;
        int p = ((jc ^ side) << 1) + h;    // j-pair index actually read at step k
        PACK_F32X2(w1a[k], w1s[(2*p) * 32 + f0], w1s[(2*p+1) * 32 + f0]);
        PACK_F32X2(w1b[k], w1s[(2*p) * 32 + f1], w1s[(2*p+1) * 32 + f1]);
    }
    unsigned long long bias_a, bias_b;
    PACK_F32X2(bias_a, b1s[f0], 0.0f);
    PACK_F32X2(bias_b, b1s[f1], 0.0f);

    unsigned long long gF0c01 = 0ULL, gF0c23 = 0ULL;
    unsigned long long gF1c01 = 0ULL, gF1c23 = 0ULL;

    #pragma unroll
    for (int ch = 0; ch < 2; ch++) {
        if (ch == 0) { CP_WAIT1(); } else { CP_WAIT0(); }
        __syncthreads();
        const float* buf = eas[ch];
        #pragma unroll
        for (int p = 0; p < 4; p++) {
            const int rs = wid * 8 + p * 2 + side;   // this lane's row
            unsigned long long hA = bias_a, hA2 = 0ULL;
            unsigned long long hB = bias_b, hB2 = 0ULL;
            const float* rowp = buf + rs * 32;
            #pragma unroll
            for (int jc = 0; jc < 8; jc++) {
                // rotated chunk: side 1 reads jc^1 -> disjoint bank quads
                ulonglong2 a = *(const ulonglong2*)(rowp + ((jc ^ side) << 2));
                FMA_F32X2(hA,  a.x, w1a[2*jc],   hA);
                FMA_F32X2(hA2, a.y, w1a[2*jc+1], hA2);
                FMA_F32X2(hB,  a.x, w1b[2*jc],   hB);
                FMA_F32X2(hB2, a.y, w1b[2*jc+1], hB2);
            }
            ADD_F32X2(hA, hA, hA2);
            ADD_F32X2(hB, hB, hB2);
            float lo, hi;
            UNPACK_F32X2(lo, hi, hA);
            float h0 = fmaxf(lo + hi, 0.0f);
            UNPACK_F32X2(lo, hi, hB);
            float h1 = fmaxf(lo + hi, 0.0f);

            ulonglong2 s2 = *(const ulonglong2*)(shp + (ch * 64 + rs) * 4);
            unsigned long long hd;
            PACK_F32X2(hd, h0, h0);
            FMA_F32X2(gF0c01, hd, s2.x, gF0c01);
            FMA_F32X2(gF0c23, hd, s2.y, gF0c23);
            PACK_F32X2(hd, h1, h1);
            FMA_F32X2(gF1c01, hd, s2.x, gF1c01);
            FMA_F32X2(gF1c23, hd, s2.y, gF1c23);
        }
    }

    // merge the two row-sides (lane ^ 16 holds the other side, same f-pair)
    {
        float a0, a1, b0, b1;
        unsigned long long o;
        o = __shfl_xor_sync(0xFFFFFFFFu, gF0c01, 16);
        UNPACK_F32X2(a0, a1, gF0c01); UNPACK_F32X2(b0, b1, o);
        float f0c0 = a0 + b0, f0c1 = a1 + b1;
        o = __shfl_xor_sync(0xFFFFFFFFu, gF0c23, 16);
        UNPACK_F32X2(a0, a1, gF0c23); UNPACK_F32X2(b0, b1, o);
        float f0c2 = a0 + b0, f0c3 = a1 + b1;
        o = __shfl_xor_sync(0xFFFFFFFFu, gF1c01, 16);
        UNPACK_F32X2(a0, a1, gF1c01); UNPACK_F32X2(b0, b1, o);
        float f1c0 = a0 + b0, f1c1 = a1 + b1;
        o = __shfl_xor_sync(0xFFFFFFFFu, gF1c23, 16);
        UNPACK_F32X2(a0, a1, gF1c23); UNPACK_F32X2(b0, b1, o);
        float f1c2 = a0 + b0, f1c3 = a1 + b1;
        if (side == 0) {
            *(float4*)(&Gp[wid][f0 * 4]) = make_float4(f0c0, f0c1, f0c2, f0c3);
            *(float4*)(&Gp[wid][f1 * 4]) = make_float4(f1c0, f1c1, f1c2, f1c3);
        }
    }

    // bias feature: G[32][c] = sum_m sh'[m][c]
    if (t < 32) {
        int cc = t & 3, mq = t >> 2;
        float s = 0.f;
        #pragma unroll 8
        for (int m = mq; m < 128; m += 8) s += shp[m * 4 + cc];
        Gp[mq][128 + cc] = s;
    }
    __syncthreads();

    if (t < 132) {
        float s = 0.f;
        #pragma unroll
        for (int g2 = 0; g2 < 8; g2++) s += Gp[g2][t];
        g_G2[blk][t] = s;
    }
}

// ---------------------------------------------------------------------------
// Kernel B (R6 best, verbatim): 2 nodes/block, 256 blocks.
// W2' streamed in 9 chunks through 4 smem buffers; o-dim packed f32x2;
// partials overlay the stage region.
// ---------------------------------------------------------------------------
#define OFF_STAGE   0
#define OFF_GS      16384
#define OFF_SIN     (OFF_GS + 264)
#define OFF_VIN     (OFF_SIN + 32)
#define OFF_WLS     (OFF_VIN + 96)
#define OFF_WLV     (OFF_WLS + 256)
#define OFF_WOS     (OFF_WLV + 256)
#define OFF_WOV     (OFF_WOS + 256)
#define OFF_OUTS    (OFF_WOV + 256)
#define OFF_OUTV    (OFF_OUTS + 32)
#define OFF_RED     (OFF_OUTV + 96)
#define OFF_DSUM    (OFF_RED + 8)
#define SMEM_FLOATS (OFF_DSUM + 1)
#define SMEM_BYTES  (SMEM_FLOATS * 4)

__device__ __forceinline__ void chunk_compute_p(
    const float* __restrict__ stage_buf, int nrows,
    const float* __restrict__ Gs, int fbase,
    const float* si, const float* x0a, const float* x1a, const float* x2a,
    unsigned long long accS[2][2], unsigned long long accV[2][6],
    int oq, int g)
{
    int f_local = g >> 4;
    int i = g & 15;
    if (f_local >= nrows) return;
    const ulonglong2* W = (const ulonglong2*)(stage_buf + f_local * 1024 + i * 16 + oq * 4);
    ulonglong2 wss = W[0];
    ulonglong2 wvv = W[64];
    ulonglong2 wsv = W[128];
    ulonglong2 wvs = W[192];
    #pragma unroll
    for (int nl = 0; nl < 2; nl++) {
        float4 gv = *(const float4*)(Gs + nl * 132 + (fbase + f_local) * 4);
        float s  = si[nl];
        float x0 = x0a[nl], x1 = x1a[nl], x2 = x2a[nl];
        float a  = gv.x * s;
        float bc = (gv.y * x0 + gv.z * x1 + gv.w * x2) * RSQRT3;
        float c0 = gv.y * s, c1 = gv.z * s, c2 = gv.w * s;
        float d0 = gv.x * x0, d1 = gv.x * x1, d2 = gv.x * x2;
        unsigned long long a2, bc2, c02, c12, c22, d02, d12, d22;
        PACK_F32X2(a2, a, a);     PACK_F32X2(bc2, bc, bc);
        PACK_F32X2(c02, c0, c0);  PACK_F32X2(c12, c1, c1);  PACK_F32X2(c22, c2, c2);
        PACK_F32X2(d02, d0, d0);  PACK_F32X2(d12, d1, d1);  PACK_F32X2(d22, d2, d2);
        FMA_F32X2(accS[nl][0], a2,  wss.x, accS[nl][0]);
        FMA_F32X2(accS[nl][1], a2,  wss.y, accS[nl][1]);
        FMA_F32X2(accS[nl][0], bc2, wvv.x, accS[nl][0]);
        FMA_F32X2(accS[nl][1], bc2, wvv.y, accS[nl][1]);
        FMA_F32X2(accV[nl][0], c02, wsv.x, accV[nl][0]);
        FMA_F32X2(accV[nl][1], c02, wsv.y, accV[nl][1]);
        FMA_F32X2(accV[nl][0], d02, wvs.x, accV[nl][0]);
        FMA_F32X2(accV[nl][1], d02, wvs.y, accV[nl][1]);
        FMA_F32X2(accV[nl][2], c12, wsv.x, accV[nl][2]);
        FMA_F32X2(accV[nl][3], c12, wsv.y, accV[nl][3]);
        FMA_F32X2(accV[nl][2], d12, wvs.x, accV[nl][2]);
        FMA_F32X2(accV[nl][3], d12, wvs.y, accV[nl][3]);
        FMA_F32X2(accV[nl][4], c22, wsv.x, accV[nl][4]);
        FMA_F32X2(accV[nl][5], c22, wsv.y, accV[nl][5]);
        FMA_F32X2(accV[nl][4], d22, wvs.x, accV[nl][4]);
        FMA_F32X2(accV[nl][5], d22, wvs.y, accV[nl][5]);
    }
}

__device__ __forceinline__ void issue_chunk(
    unsigned stage_u32, int nc, int t,
    const float* __restrict__ fc_w2, const float* __restrict__ fc_b2)
{
    unsigned dst = stage_u32 + (unsigned)(nc & 3) * 16384u + (unsigned)t * 16u;
    if (nc < 8) {
        const float* src = fc_w2 + nc * 4096 + t * 4;
        #pragma unroll
        for (int r = 0; r < 4; r++)
            CP_ASYNC16(dst + r * 4096u, src + r * 1024);
    } else {
        CP_ASYNC16(dst, fc_b2 + t * 4);
    }
    CP_COMMIT();
}

__global__ __launch_bounds__(256, 3) void node_kernel(
    const float* __restrict__ node_attr,
    const float* __restrict__ mask,
    const float* __restrict__ w_lin_in_s,
    const float* __restrict__ w_lin_in_v,
    const float* __restrict__ fc_w2,
    const float* __restrict__ fc_b2,
    const float* __restrict__ w_lin_out_s,
    const float* __restrict__ w_lin_out_v,
    float* __restrict__ out)
{
    extern __shared__ __align__(16) float sm[];
    float* stage = sm + OFF_STAGE;
    float* part  = sm + OFF_STAGE;
    float* Gs    = sm + OFF_GS;
    float* sinS  = sm + OFF_SIN;
    float* vinS  = sm + OFF_VIN;
    float* wls   = sm + OFF_WLS;
    float* wlv   = sm + OFF_WLV;
    float* wos   = sm + OFF_WOS;
    float* wov   = sm + OFF_WOV;
    float* outsS = sm + OFF_OUTS;
    float* outvS = sm + OFF_OUTV;
    float* red   = sm + OFF_RED;

    const int t = threadIdx.x;
    const int node0 = blockIdx.x * 2;
    const int b = node0 >> 8;

    const unsigned stage_u32 = (unsigned)__cvta_generic_to_shared(stage);

    issue_chunk(stage_u32, 0, t, fc_w2, fc_b2);
    issue_chunk(stage_u32, 1, t, fc_w2, fc_b2);
    issue_chunk(stage_u32, 2, t, fc_w2, fc_b2);

    wls[t] = w_lin_in_s[t];
    wlv[t] = w_lin_in_v[t];
    wos[t] = w_lin_out_s[t];
    wov[t] = w_lin_out_v[t];
    if (t < 132) {
        #pragma unroll
        for (int nl = 0; nl < 2; nl++)
            Gs[nl*132 + t] = g_G2[(node0 + nl)*2][t] + g_G2[(node0 + nl)*2 + 1][t];
    }
    {
        float mv = mask[b * NN + t];
        #pragma unroll
        for (int o = 16; o; o >>= 1) mv += __shfl_xor_sync(0xFFFFFFFFu, mv, o);
        if ((t & 31) == 0) red[t >> 5] = mv;
    }
    __syncthreads();
    if (t == 0) {
        float s = 0.f;
        #pragma unroll
        for (int i = 0; i < 8; i++) s += red[i];
        sm[OFF_DSUM] = s - 1.0f;
    }

    if (t < 128) {
        int nl = t >> 6, u = t & 63;
        const float* na = node_attr + (size_t)(node0 + nl) * 64;
        if (u < 16) {
            float s = 0.f;
            #pragma unroll
            for (int i = 0; i < 16; i++) s += na[i] * wls[i * 16 + u];
            sinS[nl*16 + u] = s * 0.25f;
        } else {
            int idx = u - 16;
            int o = idx / 3, x = idx % 3;
            float s = 0.f;
            #pragma unroll
            for (int i = 0; i < 16; i++) s += na[16 + i * 3 + x] * wlv[i * 16 + o];
            vinS[nl*48 + o * 3 + x] = s * 0.25f;
        }
    }
    __syncthreads();

    const int oq = t & 3;
    const int g  = t >> 2;

    float si[2], x0a[2], x1a[2], x2a[2];
    {
        int i = g & 15;
        #pragma unroll
        for (int nl = 0; nl < 2; nl++) {
            si[nl]  = sinS[nl*16 + i];
            x0a[nl] = vinS[nl*48 + i*3 + 0];
            x1a[nl] = vinS[nl*48 + i*3 + 1];
            x2a[nl] = vinS[nl*48 + i*3 + 2];
        }
    }

    unsigned long long accS[2][2];
    unsigned long long accV[2][6];
    #pragma unroll
    for (int nl = 0; nl < 2; nl++) {
        accS[nl][0] = accS[nl][1] = 0ULL;
        #pragma unroll
        for (int q = 0; q < 6; q++) accV[nl][q] = 0ULL;
    }

    #pragma unroll
    for (int c = 0; c < 9; c++) {
        if (c < 7) { CP_WAIT2(); } else if (c == 7) { CP_WAIT1(); } else { CP_WAIT0(); }
        __syncthreads();
        if (c + 3 <= 8) issue_chunk(stage_u32, c + 3, t, fc_w2, fc_b2);
        chunk_compute_p(stage + (c & 3) * 4096, (c < 8) ? 4 : 1, Gs, c * 4,
                        si, x0a, x1a, x2a, accS, accV, oq, g);
    }

    __syncthreads();

    #pragma unroll
    for (int nl = 0; nl < 2; nl++) {
        #pragma unroll
        for (int h = 0; h < 2; h++) {
            float v0, v1;
            UNPACK_F32X2(v0, v1, accS[nl][h]);
            part[(nl*16 + oq*4 + h*2 + 0) * 68 + g] = v0;
            part[(nl*16 + oq*4 + h*2 + 1) * 68 + g] = v1;
        }
        #pragma unroll
        for (int x = 0; x < 3; x++)
            #pragma unroll
            for (int h = 0; h < 2; h++) {
                float v0, v1;
                UNPACK_F32X2(v0, v1, accV[nl][x*2 + h]);
                int o = oq*4 + h*2;
                part[(32 + nl*48 + o*3 + x) * 68 + g] = v0;
                part[(32 + nl*48 + (o+1)*3 + x) * 68 + g] = v1;
            }
    }
    __syncthreads();

    if (t < 128) {
        float scale = INV_FAN / sm[OFF_DSUM];
        const float4* row = (const float4*)(part + t * 68);
        float s = 0.f;
        #pragma unroll
        for (int j = 0; j < 16; j++) {
            float4 v = row[j];
            s += (v.x + v.y) + (v.z + v.w);
        }
        if (t < 32) outsS[t] = s * scale;
        else        outvS[t - 32] = s * scale;
    }
    __syncthreads();

    if (t < 128) {
        int nl = t >> 6, u = t & 63;
        const float* na = node_attr + (size_t)(node0 + nl) * 64;
        float r;
        if (u < 16) {
            float s = 0.f;
            #pragma unroll
            for (int o = 0; o < 16; o++) s += outsS[nl*16 + o] * wos[o * 16 + u];
            r = s * 0.25f + na[u];
        } else {
            int idx = u - 16;
            int o2 = idx / 3, x = idx % 3;
            float s = 0.f;
            #pragma unroll
            for (int o = 0; o < 16; o++) s += outvS[nl*48 + o * 3 + x] * wov[o * 16 + o2];
            r = s * 0.25f + na[u];
        }
        out[(size_t)(node0 + nl) * 64 + u] = r;
    }
}

extern "C" void kernel_launch(void* const* d_in, const int* in_sizes, int n_in,
                              void* d_out, int out_size) {
    const float* node_attr    = (const float*)d_in[0];
    const float* edge_attr    = (const float*)d_in[1];
    const float* edge_sh      = (const float*)d_in[2];
    const float* mask         = (const float*)d_in[3];
    const float* w_lin_in_s   = (const float*)d_in[4];
    const float* w_lin_in_v   = (const float*)d_in[5];
    const float* fc_w1        = (const float*)d_in[6];
    const float* fc_b1        = (const float*)d_in[7];
    const float* fc_w2        = (const float*)d_in[8];
    const float* fc_b2        = (const float*)d_in[9];
    const float* w_lin_out_s  = (const float*)d_in[10];
    const float* w_lin_out_v  = (const float*)d_in[11];
    float* out = (float*)d_out;

    cudaFuncSetAttribute(node_kernel,
                         cudaFuncAttributeMaxDynamicSharedMemorySize, SMEM_BYTES);

    edge_kernel<<<2 * NNODE, 256>>>(edge_attr, edge_sh, mask, fc_w1, fc_b1);
    node_kernel<<<NNODE / 2, 256, SMEM_BYTES>>>(node_attr, mask,
                                    w_lin_in_s, w_lin_in_v,
                                    fc_w2, fc_b2, w_lin_out_s, w_lin_out_v, out);
}